// round 16
// baseline (speedup 1.0000x reference)
#include <cuda_runtime.h>
#include <cuda_fp16.h>
#include <math.h>
#include <cstdint>
#include <mma.h>

using namespace nvcuda;

#define N_VAR 50000
#define N_CLA 100000
#define NM    150000
#define DD    64
#define NC    1000
#define VC    64
#define KCL   128
#define NN    192
#define NE    8000
#define NSH   8
#define NITER 3
#define NEG   0.2f
#define INVSCALE 0.125f
#define NPOOLB 296

// fp16 fragments (all GEMMs)
typedef wmma::fragment<wmma::matrix_a, 16, 16, 16, __half, wmma::row_major> HA;
typedef wmma::fragment<wmma::matrix_b, 16, 16, 16, __half, wmma::col_major> HBC;
typedef wmma::fragment<wmma::matrix_b, 16, 16, 16, __half, wmma::row_major> HBR;
typedef wmma::fragment<wmma::accumulator, 16, 16, 16, float> HC;
typedef wmma::fragment<wmma::accumulator, 16, 16, 16, __half> HCH;

__device__ __forceinline__ void red_add_v4(float* p, float4 v) {
    asm volatile("red.global.add.v4.f32 [%0], {%1,%2,%3,%4};"
                 :: "l"(p), "f"(v.x), "f"(v.y), "f"(v.z), "f"(v.w) : "memory");
}
__device__ __forceinline__ void red_add_v4h2(__half* p, uint32_t a, uint32_t b,
                                             uint32_t c, uint32_t d) {
    asm volatile("red.global.add.noftz.v4.f16x2 [%0], {%1,%2,%3,%4};"
                 :: "l"(p), "r"(a), "r"(b), "r"(c), "r"(d) : "memory");
}

// ---------------- scratch ----------------------------------------------------
__device__ float  g_x   [NM * DD];
__device__ __half g_Qh  [NM * DD];
__device__ __half g_Kh  [NM * DD];
__device__ __half g_Vh  [NM * DD];
__device__ __half g_acch[NM * DD];
__device__ float  g_cnt [NM];          // raw occurrence counts
__device__ float  g_Q2  [NC * DD];
__device__ float  g_K2  [NC * DD];
__device__ float  g_V2  [NC * DD];
__device__ float  g_poolpart[NPOOLB * 128];
__device__ __half g_Wh  [3 * DD * DD]; // WQ1/WK1/WV1 as half
__device__ __half g_Woh [DD * DD];     // Wo as half

__global__ void k_zero0() {
    int t = blockIdx.x * blockDim.x + threadIdx.x;
    if (t < NM) g_cnt[t] = 0.f;
}

// weights->half AND node occurrence counts (both iteration-invariant)
__global__ void k_prep(const float* __restrict__ WQ, const float* __restrict__ WK,
                       const float* __restrict__ WV, const float* __restrict__ Wo,
                       const int* __restrict__ cvar, const int* __restrict__ ccla) {
    int i = blockIdx.x * blockDim.x + threadIdx.x;
    if (i < 4096)       g_Wh[i]        = __float2half_rn(WQ[i]);
    else if (i < 8192)  g_Wh[i]        = __float2half_rn(WK[i - 4096]);
    else if (i < 12288) g_Wh[i]        = __float2half_rn(WV[i - 8192]);
    else if (i < 16384) g_Woh[i-12288] = __float2half_rn(Wo[i - 12288]);
    if (i < NC * VC) atomicAdd(&g_cnt[cvar[i]], 1.f);
    else if (i < NC * (VC + KCL)) atomicAdd(&g_cnt[N_VAR + ccla[i - NC * VC]], 1.f);
}

// row pointer helper: iteration 0 reads directly from the harness inputs
__device__ __forceinline__ const float* xrow(const float* xv, const float* xc,
                                             int first, size_t r) {
    if (first)
        return (r < N_VAR) ? (xv + r * 64) : (xc + (r - (size_t)N_VAR) * 64);
    return g_x + r * 64;
}

// ---------------- Q/K/V projection via WMMA fp16, staged coalesced stores ----
#define PROJ_SMEM (27648 + 18432)
__global__ void __launch_bounds__(256, 4) k_proj(const float* __restrict__ xv,
                                                 const float* __restrict__ xc,
                                                 int first) {
    extern __shared__ char smem[];
    __half* Wh = (__half*)smem;                       // [3][64][72]
    __half* xs = (__half*)(smem + 27648);             // [128][72]
    int tid = threadIdx.x, wid = tid >> 5, lane = tid & 31;

    for (int i = tid; i < 3 * 64 * 16; i += 256) {
        int m = i >> 10, rem = i & 1023, d = rem >> 4, q4 = rem & 15;
        *(uint2*)(Wh + m * 4608 + d * 72 + q4 * 4) =
            *(const uint2*)(g_Wh + m * 4096 + d * 64 + q4 * 4);
    }
    size_t base = (size_t)blockIdx.x * 128;
    for (int i = tid; i < 128 * 16; i += 256) {
        int row = i >> 4, q4 = i & 15;
        size_t r = base + row;
        if (r < NM) {
            float4 v = ((const float4*)xrow(xv, xc, first, r))[q4];
            __half2 h0 = __floats2half2_rn(v.x, v.y);
            __half2 h1 = __floats2half2_rn(v.z, v.w);
            uint2 u; u.x = *(uint32_t*)&h0; u.y = *(uint32_t*)&h1;
            *(uint2*)(xs + row * 72 + q4 * 4) = u;
        }
    }
    __syncthreads();

    int rowbase = wid * 16;
    if (base + rowbase < NM) {
        HA a[4];
        #pragma unroll
        for (int k = 0; k < 4; k++)
            wmma::load_matrix_sync(a[k], xs + rowbase * 72 + k * 16, 72);
        __half* band = xs + rowbase * 72;     // dead after A-frag loads
        __half* outs[3] = {g_Qh, g_Kh, g_Vh};
        #pragma unroll
        for (int m = 0; m < 3; m++) {
            #pragma unroll
            for (int tc = 0; tc < 4; tc++) {
                HC acc;
                wmma::fill_fragment(acc, 0.f);
                #pragma unroll
                for (int k = 0; k < 4; k++) {
                    HBC b;
                    wmma::load_matrix_sync(b, Wh + m * 4608 + tc * 16 * 72 + k * 16, 72);
                    wmma::mma_sync(acc, a[k], b, acc);
                }
                HCH h;
                if (m == 0) {
                    #pragma unroll
                    for (int t = 0; t < acc.num_elements; t++)
                        h.x[t] = __float2half_rn(acc.x[t] * INVSCALE);
                } else {
                    #pragma unroll
                    for (int t = 0; t < acc.num_elements; t++)
                        h.x[t] = __float2half_rn(acc.x[t]);
                }
                wmma::store_matrix_sync(band + tc * 16, h, 72, wmma::mem_row_major);
            }
            __syncwarp();
            __half* dst = outs[m] + (base + rowbase) * 64;
            #pragma unroll
            for (int i = 0; i < 4; i++) {
                int idx = lane + 32 * i;
                int row = idx >> 3, q8 = idx & 7;
                *(uint4*)(dst + row * 64 + q8 * 8) =
                    *(const uint4*)(band + row * 72 + q8 * 8);
            }
            __syncwarp();
        }
    }
    // zero g_acch
    uint4 z4 = make_uint4(0u, 0u, 0u, 0u);
    for (int i = tid; i < 128 * 8; i += 256) {
        int row = i >> 3, q8 = i & 7;
        size_t r = base + row;
        if (r < NM) *(uint4*)(g_acch + r * 64 + q8 * 8) = z4;
    }
}

// ---------------- intra-cluster attention via WMMA fp16 ----------------------
// 1 CTA/cluster, 6 bands x 32 queries; Q prefetch overlapped with softmax.
#define OFFB_K  0
#define OFFB_V  27648
#define OFFB_Q  55296
#define OFFB_S  59904
#define OFFB_RS 72704
#define OFFB_B  72832
#define OFFB_N  73600
#define ATTN_SMEM 74368

__global__ void __launch_bounds__(384, 3) k_attn_wm(const int* __restrict__ cvar,
                                                    const int* __restrict__ ccla,
                                                    const float* __restrict__ sat,
                                                    const float* __restrict__ hw) {
    extern __shared__ char smem[];
    __half* Kh = (__half*)(smem + OFFB_K);     // [192][72]
    __half* Vh = (__half*)(smem + OFFB_V);     // [192][72]
    __half* Qh = (__half*)(smem + OFFB_Q);     // [32][72]
    __half* Sh = (__half*)(smem + OFFB_S);     // [32][200] scores -> exp (in place)
    float*  Of = (float*)(smem + OFFB_S);      // [32][72] O staging (aliases Sh)
    float*  rowsum = (float*)(smem + OFFB_RS); // [32]
    float*  bsh = (float*)(smem + OFFB_B);     // [192]
    int*    nsh = (int*)(smem + OFFB_N);       // [192]

    int c = blockIdx.x, tid = threadIdx.x, wid = tid >> 5, lane = tid & 31;
    if (tid < NN) {
        int g; float b;
        if (tid < VC) { g = cvar[c * VC + tid]; b = 0.f; }
        else { int cl = ccla[c * KCL + (tid - VC)]; g = N_VAR + cl; b = sat[cl]; }
        nsh[tid] = g; bsh[tid] = b;
    }
    float hwm = 0.25f * (hw[0] + hw[1] + hw[2] + hw[3]);
    __syncthreads();

    for (int idx = tid; idx < 192 * 8; idx += 384) {
        int row = idx >> 3, q8 = idx & 7;
        size_t o = (size_t)nsh[row] * 64;
        *(uint4*)(Kh + row * 72 + q8 * 8) = ((const uint4*)(g_Kh + o))[q8];
        *(uint4*)(Vh + row * 72 + q8 * 8) = ((const uint4*)(g_Vh + o))[q8];
    }
    // gather band-0 Q
    for (int idx = tid; idx < 32 * 8; idx += 384) {
        int row = idx >> 3, q8 = idx & 7;
        *(uint4*)(Qh + row * 72 + q8 * 8) =
            ((const uint4*)(g_Qh + (size_t)nsh[row] * 64))[q8];
    }
    __syncthreads();

    for (int band = 0; band < 6; band++) {
        // GEMM1: S[32,192] = Qh @ Kh^T, stored as half
        {
            int tr = wid & 1, tc = wid >> 1;
            HA a[4];
            #pragma unroll
            for (int k = 0; k < 4; k++)
                wmma::load_matrix_sync(a[k], Qh + tr * 16 * 72 + k * 16, 72);
            #pragma unroll
            for (int half2x = 0; half2x < 2; half2x++) {
                int tcc = tc + half2x * 6;
                HC acc;
                wmma::fill_fragment(acc, 0.f);
                #pragma unroll
                for (int k = 0; k < 4; k++) {
                    HBC bb;
                    wmma::load_matrix_sync(bb, Kh + tcc * 16 * 72 + k * 16, 72);
                    wmma::mma_sync(acc, a[k], bb, acc);
                }
                HCH h;
                #pragma unroll
                for (int t = 0; t < acc.num_elements; t++)
                    h.x[t] = __float2half_rn(acc.x[t]);
                wmma::store_matrix_sync(Sh + tr * 16 * 200 + tcc * 16, h, 200,
                                        wmma::mem_row_major);
            }
        }
        __syncthreads();

        // softmax (warps 0-7) || prefetch next band's Q (warps 8-11)
        if (tid < 256) {
            int srow = tid >> 3, c0 = tid & 7;
            __half* srw = Sh + srow * 200;
            float mx = -1e30f;
            #pragma unroll 8
            for (int i = 0; i < 24; i++) {
                int col = c0 + 8 * i;
                float s = __half2float(srw[col]) + bsh[col];
                s = (s >= 0.f) ? s : NEG * s;
                srw[col] = __float2half_rn(s);
                mx = fmaxf(mx, s);
            }
            mx = fmaxf(mx, __shfl_xor_sync(0xffffffffu, mx, 1));
            mx = fmaxf(mx, __shfl_xor_sync(0xffffffffu, mx, 2));
            mx = fmaxf(mx, __shfl_xor_sync(0xffffffffu, mx, 4));
            float sum = 0.f;
            #pragma unroll 8
            for (int i = 0; i < 24; i++) {
                int col = c0 + 8 * i;
                float e = __expf(__half2float(srw[col]) - mx);
                sum += e;
                srw[col] = __float2half_rn(e);
            }
            sum += __shfl_xor_sync(0xffffffffu, sum, 1);
            sum += __shfl_xor_sync(0xffffffffu, sum, 2);
            sum += __shfl_xor_sync(0xffffffffu, sum, 4);
            if (c0 == 0) rowsum[srow] = sum;
        } else if (band < 5) {
            for (int idx = tid - 256; idx < 32 * 8; idx += 128) {
                int row = idx >> 3, q8 = idx & 7;
                *(uint4*)(Qh + row * 72 + q8 * 8) =
                    ((const uint4*)(g_Qh + (size_t)nsh[(band + 1) * 32 + row] * 64))[q8];
            }
        }
        __syncthreads();

        // GEMM2: O[32,64] = P @ V; C-frag in regs across sync
        HC o0;
        wmma::fill_fragment(o0, 0.f);
        int tr2 = wid >> 2, tc2 = wid & 3;
        if (wid < 8) {
            #pragma unroll 4
            for (int k = 0; k < 12; k++) {
                HA a;
                wmma::load_matrix_sync(a, Sh + tr2 * 16 * 200 + k * 16, 200);
                HBR bb;
                wmma::load_matrix_sync(bb, Vh + k * 16 * 72 + tc2 * 16, 72);
                wmma::mma_sync(o0, a, bb, o0);
            }
        }
        __syncthreads();   // all reads of Sh done
        if (wid < 8) {
            wmma::store_matrix_sync(Of + tr2 * 16 * 72 + tc2 * 16, o0, 72,
                                    wmma::mem_row_major);
            __syncwarp();
            int row = lane >> 1, c8 = (lane & 1) * 8;
            int grow = tr2 * 16 + row;
            int g = nsh[band * 32 + grow];
            float scl = hwm / rowsum[grow];
            const float* src = Of + grow * 72 + tc2 * 16 + c8;
            __half* dst = g_acch + (size_t)g * 64 + tc2 * 16 + c8;
            float4 f0 = *(const float4*)(src);
            float4 f1 = *(const float4*)(src + 4);
            __half2 h0 = __floats2half2_rn(f0.x * scl, f0.y * scl);
            __half2 h1 = __floats2half2_rn(f0.z * scl, f0.w * scl);
            __half2 h2 = __floats2half2_rn(f1.x * scl, f1.y * scl);
            __half2 h3 = __floats2half2_rn(f1.z * scl, f1.w * scl);
            red_add_v4h2(dst, *(uint32_t*)&h0, *(uint32_t*)&h1,
                              *(uint32_t*)&h2, *(uint32_t*)&h3);
        }
        __syncthreads();   // Of reads done before next band's GEMM1 writes Sh
    }
}

// ---------------- finalize via WMMA fp16 (staged in dead A-band) -------------
#define FIN_SMEM (9216 + 18432)
__global__ void __launch_bounds__(256, 4) k_fin(const float* __restrict__ bo,
                                                const float* __restrict__ xv,
                                                const float* __restrict__ xc,
                                                int first) {
    extern __shared__ char smem[];
    __half* Wh = (__half*)smem;                   // [64][72] (d,k) at d*72+k
    __half* xs = (__half*)(smem + 9216);          // [128][72] acc halves / staging
    int tid = threadIdx.x, wid = tid >> 5, lane = tid & 31;

    for (int i = tid; i < 64 * 16; i += 256) {
        int d = i >> 4, q4 = i & 15;
        *(uint2*)(Wh + d * 72 + q4 * 4) = *(const uint2*)(g_Woh + d * 64 + q4 * 4);
    }
    size_t base = (size_t)blockIdx.x * 128;
    for (int i = tid; i < 128 * 8; i += 256) {
        int row = i >> 3, q8 = i & 7;
        size_t r = base + row;
        if (r < NM)
            *(uint4*)(xs + row * 72 + q8 * 8) = *(const uint4*)(g_acch + r * 64 + q8 * 8);
    }
    __syncthreads();

    int rowbase = wid * 16;
    if (base + rowbase < NM) {
        HA a[4];
        #pragma unroll
        for (int k = 0; k < 4; k++)
            wmma::load_matrix_sync(a[k], xs + rowbase * 72 + k * 16, 72);
        __half* band = xs + rowbase * 72;
        #pragma unroll
        for (int tc = 0; tc < 4; tc++) {
            HC acc;
            wmma::fill_fragment(acc, 0.f);
            #pragma unroll
            for (int k = 0; k < 4; k++) {
                HBC b;
                wmma::load_matrix_sync(b, Wh + tc * 16 * 72 + k * 16, 72);
                wmma::mma_sync(acc, a[k], b, acc);
            }
            HCH h;
            #pragma unroll
            for (int t = 0; t < acc.num_elements; t++)
                h.x[t] = __float2half_rn(acc.x[t]);
            wmma::store_matrix_sync(band + tc * 16, h, 72, wmma::mem_row_major);
        }
        __syncwarp();
        #pragma unroll
        for (int i = 0; i < 4; i++) {
            int idx = lane + 32 * i;
            int row = idx >> 3, q8 = idx & 7;
            size_t r = base + rowbase + row;
            float rc = 1.f / fmaxf(g_cnt[r], 1.f);
            uint4 u = *(const uint4*)(band + row * 72 + q8 * 8);
            __half2 h0 = *(__half2*)&u.x, h1 = *(__half2*)&u.y;
            __half2 h2 = *(__half2*)&u.z, h3 = *(__half2*)&u.w;
            float2 f0 = __half22float2(h0), f1 = __half22float2(h1);
            float2 f2 = __half22float2(h2), f3 = __half22float2(h3);
            const float* xr = xrow(xv, xc, first, r) + q8 * 8;
            float* gx = g_x + r * 64 + q8 * 8;
            const float* bb = bo + q8 * 8;
            float4 x0 = *(const float4*)xr, x1 = *(const float4*)(xr + 4);
            float4 b0 = *(const float4*)bb, b1 = *(const float4*)(bb + 4);
            x0.x += f0.x * rc + b0.x; x0.y += f0.y * rc + b0.y;
            x0.z += f1.x * rc + b0.z; x0.w += f1.y * rc + b0.w;
            x1.x += f2.x * rc + b1.x; x1.y += f2.y * rc + b1.y;
            x1.z += f3.x * rc + b1.z; x1.w += f3.y * rc + b1.w;
            *(float4*)gx = x0; *(float4*)(gx + 4) = x1;
        }
    }
}

// ---------------- cluster features + Q2/K2/V2 projection (4 clusters/CTA) ----
__global__ void __launch_bounds__(256) k_cf(const int* __restrict__ cvar,
                                            const float* __restrict__ WQ2,
                                            const float* __restrict__ WK2,
                                            const float* __restrict__ WV2) {
    __shared__ float cf[4][64];
    __shared__ int ids[4][64];
    int tid = threadIdx.x;
    int sub = tid >> 6, d = tid & 63;
    int c = blockIdx.x * 4 + sub;
    ids[sub][d] = cvar[c * VC + d];
    __syncthreads();
    float s = 0.f;
    #pragma unroll 8
    for (int v = 0; v < VC; v++) s += g_x[(size_t)ids[sub][v] * DD + d];
    cf[sub][d] = s * (1.f / 64.f);
    __syncthreads();
    float q = 0.f, k = 0.f, v = 0.f;
    #pragma unroll 8
    for (int j = 0; j < 64; j++) {
        float x = cf[sub][j];
        q = fmaf(x, WQ2[d * 64 + j], q);
        k = fmaf(x, WK2[d * 64 + j], k);
        v = fmaf(x, WV2[d * 64 + j], v);
    }
    g_Q2[c * 64 + d] = q; g_K2[c * 64 + d] = k; g_V2[c * 64 + d] = v;
}

// ---------------- inter-cluster edge scatter (GAT2, vectorized atomics) ------
__global__ void k_edge(const int* __restrict__ ei, const int* __restrict__ shv,
                       const float* __restrict__ hw) {
    int tid = threadIdx.x;
    int warp = tid >> 5, lane = tid & 31;
    int e = blockIdx.x * 8 + warp;
    if (e >= NE) return;
    int c1 = ei[e], c2 = ei[NE + e];
    float p = g_Q2[c1 * 64 + lane] * g_K2[c2 * 64 + lane]
            + g_Q2[c1 * 64 + lane + 32] * g_K2[c2 * 64 + lane + 32];
    #pragma unroll
    for (int o = 16; o > 0; o >>= 1) p += __shfl_xor_sync(0xffffffffu, p, o);
    float s = p * INVSCALE;
    float lr = (s >= 0.f) ? s : NEG * s;
    float hwm = 0.25f * (hw[0] + hw[1] + hw[2] + hw[3]);
    float a = hwm / (1.f + __expf(-lr));
    float4 v4 = make_float4(0.f, 0.f, 0.f, 0.f);
    if (lane < 16) {
        v4 = ((const float4*)(g_V2 + (size_t)c2 * 64))[lane];
        v4.x *= a; v4.y *= a; v4.z *= a; v4.w *= a;
    }
    #pragma unroll
    for (int k = 0; k < NSH; k++) {
        int sv = shv[e * NSH + k];
        if (lane < 16) red_add_v4(g_x + (size_t)sv * 64 + lane * 4, v4);
    }
}

// ---------------- pooling (atomic-free partials) + MLP readout ---------------
__global__ void __launch_bounds__(256) k_pool() {
    __shared__ float red[2 * 64];
    int tid = threadIdx.x;
    int quad = tid & 15, rowg = tid >> 4;   // 16 quads x 16 row-groups
    if (tid < 128) red[tid] = 0.f;
    __syncthreads();
    float4 sv = make_float4(0.f, 0.f, 0.f, 0.f);
    float4 sc = make_float4(0.f, 0.f, 0.f, 0.f);
    for (int r = blockIdx.x * 16 + rowg; r < NM; r += gridDim.x * 16) {
        float4 x = ((const float4*)(g_x + (size_t)r * 64))[quad];
        if (r < N_VAR) { sv.x += x.x; sv.y += x.y; sv.z += x.z; sv.w += x.w; }
        else           { sc.x += x.x; sc.y += x.y; sc.z += x.z; sc.w += x.w; }
    }
    atomicAdd(&red[quad * 4 + 0], sv.x); atomicAdd(&red[quad * 4 + 1], sv.y);
    atomicAdd(&red[quad * 4 + 2], sv.z); atomicAdd(&red[quad * 4 + 3], sv.w);
    atomicAdd(&red[64 + quad * 4 + 0], sc.x); atomicAdd(&red[64 + quad * 4 + 1], sc.y);
    atomicAdd(&red[64 + quad * 4 + 2], sc.z); atomicAdd(&red[64 + quad * 4 + 3], sc.w);
    __syncthreads();
    if (tid < 128) g_poolpart[blockIdx.x * 128 + tid] = red[tid];
}

__global__ void k_mlp(const float* __restrict__ W1, const float* __restrict__ b1,
                      const float* __restrict__ W2, const float* __restrict__ b2,
                      float* __restrict__ out) {
    __shared__ float p[128];
    __shared__ float h[64];
    int tid = threadIdx.x;
    if (tid < 128) {
        float s = 0.f;
        for (int b = 0; b < NPOOLB; b++) s += g_poolpart[b * 128 + tid];
        p[tid] = tanhf(s * (tid < 64 ? 1.f / N_VAR : 1.f / N_CLA));
    }
    __syncthreads();
    if (tid < 64) {
        float a = b1[tid];
        #pragma unroll 8
        for (int j = 0; j < 128; j++) a = fmaf(p[j], W1[tid * 128 + j], a);
        h[tid] = (a > 0.f) ? a : 0.f;
    }
    __syncthreads();
    if (tid == 0) {
        float s = b2[0];
        for (int i = 0; i < 64; i++) s = fmaf(h[i], W2[i], s);
        out[0] = s;
    }
}

// ---------------- launch ------------------------------------------------------
extern "C" void kernel_launch(void* const* d_in, const int* in_sizes, int n_in,
                              void* d_out, int out_size) {
    (void)in_sizes; (void)n_in; (void)out_size;
    const float* xv   = (const float*)d_in[0];
    const float* xc   = (const float*)d_in[1];
    const float* sat  = (const float*)d_in[2];
    const int*   cvar = (const int*)d_in[3];
    const int*   ccla = (const int*)d_in[4];
    const int*   ei   = (const int*)d_in[5];
    const int*   shv  = (const int*)d_in[6];
    const float* WQ1  = (const float*)d_in[7];
    const float* WK1  = (const float*)d_in[8];
    const float* WV1  = (const float*)d_in[9];
    const float* hw1  = (const float*)d_in[10];
    const float* Wo   = (const float*)d_in[11];
    const float* bo   = (const float*)d_in[12];
    const float* WQ2  = (const float*)d_in[13];
    const float* WK2  = (const float*)d_in[14];
    const float* WV2  = (const float*)d_in[15];
    const float* hw2  = (const float*)d_in[16];
    const float* W1   = (const float*)d_in[17];
    const float* b1   = (const float*)d_in[18];
    const float* W2   = (const float*)d_in[19];
    const float* b2   = (const float*)d_in[20];

    cudaFuncSetAttribute(k_proj,    cudaFuncAttributeMaxDynamicSharedMemorySize, PROJ_SMEM);
    cudaFuncSetAttribute(k_attn_wm, cudaFuncAttributeMaxDynamicSharedMemorySize, ATTN_SMEM);
    cudaFuncSetAttribute(k_fin,     cudaFuncAttributeMaxDynamicSharedMemorySize, FIN_SMEM);

    k_zero0<<<(NM + 255) / 256, 256>>>();
    k_prep<<<(NC * (VC + KCL) + 255) / 256, 256>>>(WQ1, WK1, WV1, Wo, cvar, ccla);
    const int blocks128 = (NM + 127) / 128;
    for (int it = 0; it < NITER; it++) {
        k_proj<<<blocks128, 256, PROJ_SMEM>>>(xv, xc, it == 0);
        k_attn_wm<<<NC, 384, ATTN_SMEM>>>(cvar, ccla, sat, hw1);
        k_fin<<<blocks128, 256, FIN_SMEM>>>(bo, xv, xc, it == 0);
        k_cf<<<NC / 4, 256>>>(cvar, WQ2, WK2, WV2);
        k_edge<<<(NE + 7) / 8, 256>>>(ei, shv, hw2);
    }
    k_pool<<<NPOOLB, 256>>>();
    k_mlp<<<1, 128>>>(W1, b1, W2, b2, (float*)d_out);
}